// round 3
// baseline (speedup 1.0000x reference)
#include <cuda_runtime.h>
#include <cuda_bf16.h>
#include <cstdint>

#define DINLINE __device__ __forceinline__

// ---------------- problem constants ----------------
constexpr int C_    = 32;
constexpr int SP    = 13824;              // 24^3 spatial positions per (b, t)
constexpr long XSTR = 884736;             // 96^3, per-channel stride in x/out
constexpr int MTILES = 432;               // 55296 / 128
constexpr int NTILES = 4;                 // 1024 / 256
constexpr int KCHUNKS = 16;               // 1024 / 64
constexpr int A_TILE = 16384;             // 128 rows x 128B (64 bf16)
constexpr int B_TILE = 32768;             // 256 rows x 128B
constexpr int NITER  = 48;                // 3 passes x 16 chunks
constexpr int STAGE_BYTES = A_TILE + B_TILE;   // 49152
constexpr int NSTAGE = 4;
constexpr int SMEM_DYN = NSTAGE * STAGE_BYTES; // 196608

// ---------------- scratch (static device globals; no allocation) ----------------
__device__ __align__(1024) __nv_bfloat16 g_Xh[(size_t)MTILES * KCHUNKS * 8192];
__device__ __align__(1024) __nv_bfloat16 g_Xl[(size_t)MTILES * KCHUNKS * 8192];
__device__ __align__(1024) __nv_bfloat16 g_Wh[(size_t)NTILES * KCHUNKS * 16384];
__device__ __align__(1024) __nv_bfloat16 g_Wl[(size_t)NTILES * KCHUNKS * 16384];

// ---------------- helpers ----------------
DINLINE uint32_t smem_u32(const void* p) {
    uint32_t a;
    asm("{ .reg .u64 t; cvta.to.shared.u64 t, %1; cvt.u32.u64 %0, t; }" : "=r"(a) : "l"(p));
    return a;
}
DINLINE uint32_t swz(uint32_t o) { return o ^ ((o >> 3) & 0x70); }

DINLINE void cp_async16(uint32_t dst, const void* src) {
    asm volatile("cp.async.cg.shared.global [%0], [%1], 16;" :: "r"(dst), "l"(src));
}
#define CP_COMMIT() asm volatile("cp.async.commit_group;" ::: "memory")
#define CP_WAIT2()  asm volatile("cp.async.wait_group 2;" ::: "memory")
#define CP_WAIT0()  asm volatile("cp.async.wait_group 0;" ::: "memory")

DINLINE void ldsm_x4(uint32_t r[4], uint32_t addr) {
    asm volatile("ldmatrix.sync.aligned.m8n8.x4.shared.b16 {%0,%1,%2,%3}, [%4];"
                 : "=r"(r[0]), "=r"(r[1]), "=r"(r[2]), "=r"(r[3]) : "r"(addr));
}
DINLINE void mma16816(float c[4], const uint32_t a[4], uint32_t b0, uint32_t b1) {
    asm volatile(
        "mma.sync.aligned.m16n8k16.row.col.f32.bf16.bf16.f32 "
        "{%0,%1,%2,%3}, {%4,%5,%6,%7}, {%8,%9}, {%0,%1,%2,%3};"
        : "+f"(c[0]), "+f"(c[1]), "+f"(c[2]), "+f"(c[3])
        : "r"(a[0]), "r"(a[1]), "r"(a[2]), "r"(a[3]), "r"(b0), "r"(b1));
}

// ---------------- prepass: x -> rolled, split bf16 hi/lo, pre-swizzled A tiles ----------------
__global__ void __launch_bounds__(128) prepass_x(const float* __restrict__ x) {
    __shared__ __align__(16) __nv_bfloat16 shh[8192];
    __shared__ __align__(16) __nv_bfloat16 shl[8192];
    const int bx  = blockIdx.x;          // = mt*16 + kc
    const int mt  = bx >> 4;
    const int kc  = bx & 15;
    const int tid = threadIdx.x;
    const int bg  = mt / 108;
    const int b   = bg >> 1;
    const int g   = bg & 1;
    const int sp0 = (mt % 108) * 128;
    const float* xb = x + (size_t)b * C_ * XSTR + sp0 + tid;

    #pragma unroll 8
    for (int j = 0; j < 64; ++j) {
        const int k = kc * 64 + j;
        const int c = k & 31;
        const int s = k >> 5;
        const int t = (g * 32 + s + 48) & 63;
        const float v = xb[(size_t)c * XSTR + (size_t)t * SP];
        const __nv_bfloat16 hi = __float2bfloat16(v);
        const __nv_bfloat16 lo = __float2bfloat16(v - __bfloat162float(hi));
        const uint32_t off = swz((uint32_t)tid * 128 + (uint32_t)j * 2);
        *(__nv_bfloat16*)((char*)shh + off) = hi;
        *(__nv_bfloat16*)((char*)shl + off) = lo;
    }
    __syncthreads();
    const uint4* s4h = (const uint4*)shh;
    const uint4* s4l = (const uint4*)shl;
    uint4* dh = (uint4*)((char*)g_Xh + (size_t)bx * A_TILE);
    uint4* dl = (uint4*)((char*)g_Xl + (size_t)bx * A_TILE);
    #pragma unroll
    for (int i = tid; i < 1024; i += 128) { dh[i] = s4h[i]; dl[i] = s4l[i]; }
}

// ---------------- prepass: W -> split bf16 hi/lo, pre-swizzled B tiles ----------------
__global__ void __launch_bounds__(128) prepass_w(const float* __restrict__ W) {
    const int bx  = blockIdx.x;          // = nt*16 + kc
    const int nt  = bx >> 4;
    const int kc  = bx & 15;
    const int tid = threadIdx.x;
    const int j   = tid & 63;
    char* dh = (char*)g_Wh + (size_t)bx * B_TILE;
    char* dl = (char*)g_Wl + (size_t)bx * B_TILE;
    for (int r = (tid >> 6); r < 256; r += 2) {
        const int o = nt * 256 + r;
        const float v = W[(size_t)o * 1024 + kc * 64 + j];
        const __nv_bfloat16 hi = __float2bfloat16(v);
        const __nv_bfloat16 lo = __float2bfloat16(v - __bfloat162float(hi));
        const uint32_t off = swz((uint32_t)r * 128 + (uint32_t)j * 2);
        *(__nv_bfloat16*)(dh + off) = hi;
        *(__nv_bfloat16*)(dl + off) = lo;
    }
}

// ---------------- GEMM: mma.sync bf16, CTA 128x256, 16 warps (32x64 each) ----------------
DINLINE void issue_loads(int it, int s, int mt, int nt, int tid, uint32_t smem_base) {
    const int pass = it >> 4;
    const int kc   = it & 15;
    const char* aSrc = (const char*)(pass < 2 ? g_Xh : g_Xl) + (size_t)(mt * 16 + kc) * A_TILE;
    const char* bSrc = (const char*)(pass == 1 ? g_Wl : g_Wh) + (size_t)(nt * 16 + kc) * B_TILE;
    const uint32_t sA = smem_base + s * STAGE_BYTES;
    const uint32_t sB = sA + A_TILE;
    #pragma unroll
    for (int i = 0; i < 2; ++i) {
        const uint32_t o = (uint32_t)i * 8192 + (uint32_t)tid * 16;
        cp_async16(sA + o, aSrc + o);
    }
    #pragma unroll
    for (int i = 0; i < 4; ++i) {
        const uint32_t o = (uint32_t)i * 8192 + (uint32_t)tid * 16;
        cp_async16(sB + o, bSrc + o);
    }
}

__global__ void __launch_bounds__(512, 1) gemm_k(const float* __restrict__ bias,
                                                 float* __restrict__ out) {
    extern __shared__ __align__(1024) char smem[];
    const uint32_t smem_base = smem_u32(smem);
    const int tid = threadIdx.x;
    const int l   = tid & 31;
    const int wid = tid >> 5;
    const int wm  = wid & 3;     // m 32-block
    const int wn  = wid >> 2;    // n 64-block
    const int bx  = blockIdx.x;
    const int nt  = bx & 3;
    const int mt  = bx >> 2;

    // per-lane ldmatrix address components
    // A: m-block mb: row = wm*32 + mb*16 + (l&15); 16B-half = l>>4
    uint32_t a_off[2], a_ph[2];
    #pragma unroll
    for (int mb = 0; mb < 2; ++mb) {
        const int row = wm * 32 + mb * 16 + (l & 15);
        a_off[mb] = (uint32_t)row * 128;
        a_ph[mb]  = (uint32_t)(row & 7) * 16;
    }
    const uint32_t a_half = (uint32_t)(l >> 4) * 16;
    // B (non-trans): mat = l>>3; row = wn*64 + nb2*16 + (mat>>1)*8 + (l&7); half = (mat&1)*16
    const int bmat = l >> 3;
    uint32_t b_off[4], b_ph[4];
    #pragma unroll
    for (int nb2 = 0; nb2 < 4; ++nb2) {
        const int row = wn * 64 + nb2 * 16 + (bmat >> 1) * 8 + (l & 7);
        b_off[nb2] = (uint32_t)row * 128;
        b_ph[nb2]  = (uint32_t)(row & 7) * 16;
    }
    const uint32_t b_half = (uint32_t)(bmat & 1) * 16;

    float acc[2][8][4];
    #pragma unroll
    for (int mb = 0; mb < 2; ++mb)
        #pragma unroll
        for (int nb = 0; nb < 8; ++nb)
            #pragma unroll
            for (int i = 0; i < 4; ++i) acc[mb][nb][i] = 0.f;

    // prologue: stages 0,1,2
    issue_loads(0, 0, mt, nt, tid, smem_base); CP_COMMIT();
    issue_loads(1, 1, mt, nt, tid, smem_base); CP_COMMIT();
    issue_loads(2, 2, mt, nt, tid, smem_base); CP_COMMIT();

    for (int it = 0; it < NITER; ++it) {
        const int s = it & 3;
        CP_WAIT2();
        __syncthreads();
        if (it + 3 < NITER) issue_loads(it + 3, (it + 3) & 3, mt, nt, tid, smem_base);
        CP_COMMIT();

        const uint32_t sA = smem_base + s * STAGE_BYTES;
        const uint32_t sB = sA + A_TILE;
        #pragma unroll
        for (int kk = 0; kk < 4; ++kk) {
            uint32_t a[2][4];
            #pragma unroll
            for (int mb = 0; mb < 2; ++mb)
                ldsm_x4(a[mb], sA + a_off[mb] + (((uint32_t)kk * 32 + a_half) ^ a_ph[mb]));
            uint32_t bf[8][2];
            #pragma unroll
            for (int nb2 = 0; nb2 < 4; ++nb2) {
                uint32_t r[4];
                ldsm_x4(r, sB + b_off[nb2] + (((uint32_t)kk * 32 + b_half) ^ b_ph[nb2]));
                bf[nb2 * 2][0]     = r[0]; bf[nb2 * 2][1]     = r[1];
                bf[nb2 * 2 + 1][0] = r[2]; bf[nb2 * 2 + 1][1] = r[3];
            }
            #pragma unroll
            for (int mb = 0; mb < 2; ++mb)
                #pragma unroll
                for (int nb = 0; nb < 8; ++nb)
                    mma16816(acc[mb][nb], a[mb], bf[nb][0], bf[nb][1]);
        }
    }
    CP_WAIT0();
    __syncthreads();

    // ---------------- epilogue: transpose C via SMEM, coalesced scatter ----------------
    float* sC = (float*)smem;            // 128 rows x 34 floats (padded)
    const int bg = mt / 108;
    const int b  = bg >> 1;
    const int g  = bg & 1;
    const int sp0 = (mt % 108) * 128;

    const int col  = tid >> 4;           // 0..31
    const int rb   = (tid & 15) * 8;     // row base, 8 rows per thread
    float* outB = out + (size_t)b * C_ * XSTR + sp0;

    #pragma unroll
    for (int p = 0; p < 8; ++p) {        // 32-col passes over the 256-wide tile
        if (wn == (p >> 1)) {
            const int nbb = (p & 1) * 4; // first n8-block of this pass within warp
            #pragma unroll
            for (int mb = 0; mb < 2; ++mb) {
                #pragma unroll
                for (int nbl = 0; nbl < 4; ++nbl) {
                    const int nb  = nbb + nbl;
                    const int row = wm * 32 + mb * 16 + (l >> 2);
                    const int cc  = nbl * 8 + (l & 3) * 2;
                    *(float2*)&sC[row * 34 + cc]       = *(float2*)&acc[mb][nb][0];
                    *(float2*)&sC[(row + 8) * 34 + cc] = *(float2*)&acc[mb][nb][2];
                }
            }
        }
        __syncthreads();
        {
            const int o  = nt * 256 + p * 32 + col;
            const int sv = o >> 5;
            const int c  = o & 31;
            const int tp = (g * 32 + sv + 48) & 63;
            const float bia = __ldg(&bias[o]);
            float v[8];
            #pragma unroll
            for (int i = 0; i < 8; ++i) v[i] = sC[(rb + i) * 34 + col] + bia;
            float* dst = outB + (size_t)c * XSTR + (size_t)tp * SP + rb;
            *(float4*)&dst[0] = *(float4*)&v[0];
            *(float4*)&dst[4] = *(float4*)&v[4];
        }
        __syncthreads();
    }
}

// ---------------- host ----------------
extern "C" void kernel_launch(void* const* d_in, const int* in_sizes, int n_in,
                              void* d_out, int out_size) {
    const float* x    = (const float*)d_in[0];
    const float* W    = (const float*)d_in[1];
    const float* bias = (const float*)d_in[2];
    float* out = (float*)d_out;

    cudaFuncSetAttribute(gemm_k, cudaFuncAttributeMaxDynamicSharedMemorySize, SMEM_DYN);

    prepass_x<<<MTILES * KCHUNKS, 128>>>(x);                 // 6912 blocks
    prepass_w<<<NTILES * KCHUNKS, 128>>>(W);                 // 64 blocks
    gemm_k<<<MTILES * NTILES, 512, SMEM_DYN>>>(bias, out);   // 1728 blocks
}

// round 4
// speedup vs baseline: 1.1167x; 1.1167x over previous
#include <cuda_runtime.h>
#include <cuda_bf16.h>
#include <cstdint>

#define DINLINE __device__ __forceinline__

// ---------------- problem constants ----------------
constexpr int C_    = 32;
constexpr int SP    = 13824;              // 24^3 spatial positions per (b, t)
constexpr long XSTR = 884736;             // 96^3, per-channel stride in x/out
constexpr int MTILES = 432;               // 55296 / 128
constexpr int NTILES = 4;                 // 1024 / 256
constexpr int KCHUNKS = 16;               // 1024 / 64
constexpr int A_TILE = 16384;             // 128 rows x 128B (64 bf16)
constexpr int B_TILE = 32768;             // 256 rows x 128B
constexpr int STAGE_BYTES = 2 * A_TILE + 2 * B_TILE;  // 98304: Ah,Al,Bh,Bl
constexpr int NSTAGE = 2;
constexpr int SMEM_DYN = NSTAGE * STAGE_BYTES;        // 196608

// ---------------- scratch (static device globals; no allocation) ----------------
__device__ __align__(1024) __nv_bfloat16 g_Xh[(size_t)MTILES * KCHUNKS * 8192];
__device__ __align__(1024) __nv_bfloat16 g_Xl[(size_t)MTILES * KCHUNKS * 8192];
__device__ __align__(1024) __nv_bfloat16 g_Wh[(size_t)NTILES * KCHUNKS * 16384];
__device__ __align__(1024) __nv_bfloat16 g_Wl[(size_t)NTILES * KCHUNKS * 16384];

// ---------------- helpers ----------------
DINLINE uint32_t smem_u32(const void* p) {
    uint32_t a;
    asm("{ .reg .u64 t; cvta.to.shared.u64 t, %1; cvt.u32.u64 %0, t; }" : "=r"(a) : "l"(p));
    return a;
}
DINLINE uint32_t swz(uint32_t o) { return o ^ ((o >> 3) & 0x70); }

DINLINE void cp_async16(uint32_t dst, const void* src) {
    asm volatile("cp.async.cg.shared.global [%0], [%1], 16;" :: "r"(dst), "l"(src));
}
#define CP_COMMIT() asm volatile("cp.async.commit_group;" ::: "memory")
#define CP_WAIT1()  asm volatile("cp.async.wait_group 1;" ::: "memory")
#define CP_WAIT0()  asm volatile("cp.async.wait_group 0;" ::: "memory")

DINLINE void ldsm_x4(uint32_t r[4], uint32_t addr) {
    asm volatile("ldmatrix.sync.aligned.m8n8.x4.shared.b16 {%0,%1,%2,%3}, [%4];"
                 : "=r"(r[0]), "=r"(r[1]), "=r"(r[2]), "=r"(r[3]) : "r"(addr));
}
DINLINE void mma16816(float c[4], const uint32_t a[4], uint32_t b0, uint32_t b1) {
    asm volatile(
        "mma.sync.aligned.m16n8k16.row.col.f32.bf16.bf16.f32 "
        "{%0,%1,%2,%3}, {%4,%5,%6,%7}, {%8,%9}, {%0,%1,%2,%3};"
        : "+f"(c[0]), "+f"(c[1]), "+f"(c[2]), "+f"(c[3])
        : "r"(a[0]), "r"(a[1]), "r"(a[2]), "r"(a[3]), "r"(b0), "r"(b1));
}

// ---------------- prepass: x -> rolled, split bf16 hi/lo, pre-swizzled A tiles ----------------
__global__ void __launch_bounds__(128) prepass_x(const float* __restrict__ x) {
    __shared__ __align__(16) __nv_bfloat16 shh[8192];
    __shared__ __align__(16) __nv_bfloat16 shl[8192];
    const int bx  = blockIdx.x;          // = mt*16 + kc
    const int mt  = bx >> 4;
    const int kc  = bx & 15;
    const int tid = threadIdx.x;
    const int bg  = mt / 108;
    const int b   = bg >> 1;
    const int g   = bg & 1;
    const int sp0 = (mt % 108) * 128;
    const float* xb = x + (size_t)b * C_ * XSTR + sp0 + tid;

    #pragma unroll 8
    for (int j = 0; j < 64; ++j) {
        const int k = kc * 64 + j;
        const int c = k & 31;
        const int s = k >> 5;
        const int t = (g * 32 + s + 48) & 63;
        const float v = xb[(size_t)c * XSTR + (size_t)t * SP];
        const __nv_bfloat16 hi = __float2bfloat16(v);
        const __nv_bfloat16 lo = __float2bfloat16(v - __bfloat162float(hi));
        const uint32_t off = swz((uint32_t)tid * 128 + (uint32_t)j * 2);
        *(__nv_bfloat16*)((char*)shh + off) = hi;
        *(__nv_bfloat16*)((char*)shl + off) = lo;
    }
    __syncthreads();
    const uint4* s4h = (const uint4*)shh;
    const uint4* s4l = (const uint4*)shl;
    uint4* dh = (uint4*)((char*)g_Xh + (size_t)bx * A_TILE);
    uint4* dl = (uint4*)((char*)g_Xl + (size_t)bx * A_TILE);
    #pragma unroll
    for (int i = tid; i < 1024; i += 128) { dh[i] = s4h[i]; dl[i] = s4l[i]; }
}

// ---------------- prepass: W -> split bf16 hi/lo, pre-swizzled B tiles ----------------
__global__ void __launch_bounds__(128) prepass_w(const float* __restrict__ W) {
    const int bx  = blockIdx.x;          // = nt*16 + kc
    const int nt  = bx >> 4;
    const int kc  = bx & 15;
    const int tid = threadIdx.x;
    const int j   = tid & 63;
    char* dh = (char*)g_Wh + (size_t)bx * B_TILE;
    char* dl = (char*)g_Wl + (size_t)bx * B_TILE;
    for (int r = (tid >> 6); r < 256; r += 2) {
        const int o = nt * 256 + r;
        const float v = W[(size_t)o * 1024 + kc * 64 + j];
        const __nv_bfloat16 hi = __float2bfloat16(v);
        const __nv_bfloat16 lo = __float2bfloat16(v - __bfloat162float(hi));
        const uint32_t off = swz((uint32_t)r * 128 + (uint32_t)j * 2);
        *(__nv_bfloat16*)(dh + off) = hi;
        *(__nv_bfloat16*)(dl + off) = lo;
    }
}

// ---------------- GEMM: mma.sync bf16, CTA 128x256, fused 3-product single K sweep ----------------
DINLINE void issue_loads(int kc, int s, int mt, int nt, int tid, uint32_t smem_base) {
    const char* aH = (const char*)g_Xh + (size_t)(mt * 16 + kc) * A_TILE;
    const char* aL = (const char*)g_Xl + (size_t)(mt * 16 + kc) * A_TILE;
    const char* bH = (const char*)g_Wh + (size_t)(nt * 16 + kc) * B_TILE;
    const char* bL = (const char*)g_Wl + (size_t)(nt * 16 + kc) * B_TILE;
    const uint32_t sAh = smem_base + s * STAGE_BYTES;
    const uint32_t sAl = sAh + A_TILE;
    const uint32_t sBh = sAh + 2 * A_TILE;
    const uint32_t sBl = sBh + B_TILE;
    #pragma unroll
    for (int i = 0; i < 2; ++i) {
        const uint32_t o = (uint32_t)i * 8192 + (uint32_t)tid * 16;
        cp_async16(sAh + o, aH + o);
        cp_async16(sAl + o, aL + o);
    }
    #pragma unroll
    for (int i = 0; i < 4; ++i) {
        const uint32_t o = (uint32_t)i * 8192 + (uint32_t)tid * 16;
        cp_async16(sBh + o, bH + o);
        cp_async16(sBl + o, bL + o);
    }
}

__global__ void __launch_bounds__(512, 1) gemm_k(const float* __restrict__ bias,
                                                 float* __restrict__ out) {
    extern __shared__ __align__(1024) char smem[];
    const uint32_t smem_base = smem_u32(smem);
    const int tid = threadIdx.x;
    const int l   = tid & 31;
    const int wid = tid >> 5;
    const int wm  = wid & 3;     // m 32-block
    const int wn  = wid >> 2;    // n 64-block
    const int bx  = blockIdx.x;
    const int nt  = bx & 3;
    const int mt  = bx >> 2;

    // per-lane ldmatrix address components
    uint32_t a_off[2], a_ph[2];
    #pragma unroll
    for (int mb = 0; mb < 2; ++mb) {
        const int row = wm * 32 + mb * 16 + (l & 15);
        a_off[mb] = (uint32_t)row * 128;
        a_ph[mb]  = (uint32_t)(row & 7) * 16;
    }
    const uint32_t a_half = (uint32_t)(l >> 4) * 16;
    const int bmat = l >> 3;
    uint32_t b_off[4], b_ph[4];
    #pragma unroll
    for (int nb2 = 0; nb2 < 4; ++nb2) {
        const int row = wn * 64 + nb2 * 16 + (bmat >> 1) * 8 + (l & 7);
        b_off[nb2] = (uint32_t)row * 128;
        b_ph[nb2]  = (uint32_t)(row & 7) * 16;
    }
    const uint32_t b_half = (uint32_t)(bmat & 1) * 16;

    float acc[2][8][4];
    #pragma unroll
    for (int mb = 0; mb < 2; ++mb)
        #pragma unroll
        for (int nb = 0; nb < 8; ++nb)
            #pragma unroll
            for (int i = 0; i < 4; ++i) acc[mb][nb][i] = 0.f;

    // prologue: stages 0,1
    issue_loads(0, 0, mt, nt, tid, smem_base); CP_COMMIT();
    issue_loads(1, 1, mt, nt, tid, smem_base); CP_COMMIT();

    for (int it = 0; it < KCHUNKS; ++it) {
        const int s = it & 1;
        CP_WAIT1();
        __syncthreads();

        const uint32_t sAh = smem_base + s * STAGE_BYTES;
        const uint32_t sAl = sAh + A_TILE;
        const uint32_t sBh = sAh + 2 * A_TILE;
        const uint32_t sBl = sBh + B_TILE;

        #pragma unroll
        for (int kk = 0; kk < 4; ++kk) {
            const uint32_t ka = (uint32_t)kk * 32 + a_half;
            const uint32_t kb = (uint32_t)kk * 32 + b_half;
            uint32_t ah[2][4], al[2][4], bf[8][2];
            // load A-hi fragments (shared by hh and hl products)
            #pragma unroll
            for (int mb = 0; mb < 2; ++mb)
                ldsm_x4(ah[mb], sAh + a_off[mb] + (ka ^ a_ph[mb]));
            // B-hi fragments
            #pragma unroll
            for (int nb2 = 0; nb2 < 4; ++nb2) {
                uint32_t r[4];
                ldsm_x4(r, sBh + b_off[nb2] + (kb ^ b_ph[nb2]));
                bf[nb2 * 2][0]     = r[0]; bf[nb2 * 2][1]     = r[1];
                bf[nb2 * 2 + 1][0] = r[2]; bf[nb2 * 2 + 1][1] = r[3];
            }
            // hh
            #pragma unroll
            for (int mb = 0; mb < 2; ++mb)
                #pragma unroll
                for (int nb = 0; nb < 8; ++nb)
                    mma16816(acc[mb][nb], ah[mb], bf[nb][0], bf[nb][1]);
            // A-lo fragments, lh (al x Bh)
            #pragma unroll
            for (int mb = 0; mb < 2; ++mb)
                ldsm_x4(al[mb], sAl + a_off[mb] + (ka ^ a_ph[mb]));
            #pragma unroll
            for (int mb = 0; mb < 2; ++mb)
                #pragma unroll
                for (int nb = 0; nb < 8; ++nb)
                    mma16816(acc[mb][nb], al[mb], bf[nb][0], bf[nb][1]);
            // B-lo fragments (reuse bf regs), hl (ah x Bl)
            #pragma unroll
            for (int nb2 = 0; nb2 < 4; ++nb2) {
                uint32_t r[4];
                ldsm_x4(r, sBl + b_off[nb2] + (kb ^ b_ph[nb2]));
                bf[nb2 * 2][0]     = r[0]; bf[nb2 * 2][1]     = r[1];
                bf[nb2 * 2 + 1][0] = r[2]; bf[nb2 * 2 + 1][1] = r[3];
            }
            #pragma unroll
            for (int mb = 0; mb < 2; ++mb)
                #pragma unroll
                for (int nb = 0; nb < 8; ++nb)
                    mma16816(acc[mb][nb], ah[mb], bf[nb][0], bf[nb][1]);
        }

        __syncthreads();
        if (it + 2 < KCHUNKS) issue_loads(it + 2, s, mt, nt, tid, smem_base);
        CP_COMMIT();
    }
    CP_WAIT0();
    __syncthreads();

    // ---------------- epilogue: transpose C via SMEM, coalesced scatter ----------------
    float* sC = (float*)smem;            // 128 rows x 34 floats (padded)
    const int bg = mt / 108;
    const int b  = bg >> 1;
    const int g  = bg & 1;
    const int sp0 = (mt % 108) * 128;

    const int col  = tid >> 4;           // 0..31
    const int rb   = (tid & 15) * 8;     // row base, 8 rows per thread
    float* outB = out + (size_t)b * C_ * XSTR + sp0;

    #pragma unroll
    for (int p = 0; p < 8; ++p) {        // 32-col passes over the 256-wide tile
        if (wn == (p >> 1)) {
            const int nbb = (p & 1) * 4;
            #pragma unroll
            for (int mb = 0; mb < 2; ++mb) {
                #pragma unroll
                for (int nbl = 0; nbl < 4; ++nbl) {
                    const int nb  = nbb + nbl;
                    const int row = wm * 32 + mb * 16 + (l >> 2);
                    const int cc  = nbl * 8 + (l & 3) * 2;
                    *(float2*)&sC[row * 34 + cc]       = *(float2*)&acc[mb][nb][0];
                    *(float2*)&sC[(row + 8) * 34 + cc] = *(float2*)&acc[mb][nb][2];
                }
            }
        }
        __syncthreads();
        {
            const int o  = nt * 256 + p * 32 + col;
            const int sv = o >> 5;
            const int c  = o & 31;
            const int tp = (g * 32 + sv + 48) & 63;
            const float bia = __ldg(&bias[o]);
            float v[8];
            #pragma unroll
            for (int i = 0; i < 8; ++i) v[i] = sC[(rb + i) * 34 + col] + bia;
            float* dst = outB + (size_t)c * XSTR + (size_t)tp * SP + rb;
            *(float4*)&dst[0] = *(float4*)&v[0];
            *(float4*)&dst[4] = *(float4*)&v[4];
        }
        __syncthreads();
    }
}

// ---------------- host ----------------
extern "C" void kernel_launch(void* const* d_in, const int* in_sizes, int n_in,
                              void* d_out, int out_size) {
    const float* x    = (const float*)d_in[0];
    const float* W    = (const float*)d_in[1];
    const float* bias = (const float*)d_in[2];
    float* out = (float*)d_out;

    cudaFuncSetAttribute(gemm_k, cudaFuncAttributeMaxDynamicSharedMemorySize, SMEM_DYN);

    prepass_x<<<MTILES * KCHUNKS, 128>>>(x);                 // 6912 blocks
    prepass_w<<<NTILES * KCHUNKS, 128>>>(W);                 // 64 blocks
    gemm_k<<<MTILES * NTILES, 512, SMEM_DYN>>>(bias, out);   // 1728 blocks
}

// round 5
// speedup vs baseline: 1.4979x; 1.3414x over previous
#include <cuda_runtime.h>
#include <cuda_fp16.h>
#include <cstdint>

#define DINLINE __device__ __forceinline__

// ---------------- problem constants ----------------
constexpr int C_    = 32;
constexpr int SP    = 13824;              // 24^3 spatial positions per (b, t)
constexpr long XSTR = 884736;             // 96^3, per-channel stride in x/out
constexpr int MTILES = 432;               // 55296 / 128
constexpr int NTILES = 4;                 // 1024 / 256
constexpr int KCHUNKS = 16;               // 1024 / 64
constexpr int A_TILE = 16384;             // 128 rows x 128B (64 fp16)
constexpr int B_TILE = 32768;             // 256 rows x 128B
constexpr int STAGE_BYTES = A_TILE + 2 * B_TILE;      // 81920: Ah,Bh,Bl
constexpr int NSTAGE = 2;
constexpr int SMEM_DYN = NSTAGE * STAGE_BYTES;        // 163840

// ---------------- scratch (static device globals; no allocation) ----------------
__device__ __align__(1024) __half g_Xh[(size_t)MTILES * KCHUNKS * 8192];
__device__ __align__(1024) __half g_Wh[(size_t)NTILES * KCHUNKS * 16384];
__device__ __align__(1024) __half g_Wl[(size_t)NTILES * KCHUNKS * 16384];

// ---------------- helpers ----------------
DINLINE uint32_t smem_u32(const void* p) {
    uint32_t a;
    asm("{ .reg .u64 t; cvta.to.shared.u64 t, %1; cvt.u32.u64 %0, t; }" : "=r"(a) : "l"(p));
    return a;
}
DINLINE uint32_t swz(uint32_t o) { return o ^ ((o >> 3) & 0x70); }

DINLINE void cp_async16(uint32_t dst, const void* src) {
    asm volatile("cp.async.cg.shared.global [%0], [%1], 16;" :: "r"(dst), "l"(src));
}
#define CP_COMMIT() asm volatile("cp.async.commit_group;" ::: "memory")
#define CP_WAIT1()  asm volatile("cp.async.wait_group 1;" ::: "memory")
#define CP_WAIT0()  asm volatile("cp.async.wait_group 0;" ::: "memory")

DINLINE void ldsm_x4(uint32_t r[4], uint32_t addr) {
    asm volatile("ldmatrix.sync.aligned.m8n8.x4.shared.b16 {%0,%1,%2,%3}, [%4];"
                 : "=r"(r[0]), "=r"(r[1]), "=r"(r[2]), "=r"(r[3]) : "r"(addr));
}
DINLINE void mma16816(float c[4], const uint32_t a[4], uint32_t b0, uint32_t b1) {
    asm volatile(
        "mma.sync.aligned.m16n8k16.row.col.f32.f16.f16.f32 "
        "{%0,%1,%2,%3}, {%4,%5,%6,%7}, {%8,%9}, {%0,%1,%2,%3};"
        : "+f"(c[0]), "+f"(c[1]), "+f"(c[2]), "+f"(c[3])
        : "r"(a[0]), "r"(a[1]), "r"(a[2]), "r"(a[3]), "r"(b0), "r"(b1));
}

// ---------------- prepass: x -> rolled fp16, pre-swizzled A tiles ----------------
__global__ void __launch_bounds__(128) prepass_x(const float* __restrict__ x) {
    __shared__ __align__(16) __half shh[8192];
    const int bx  = blockIdx.x;          // = mt*16 + kc
    const int mt  = bx >> 4;
    const int kc  = bx & 15;
    const int tid = threadIdx.x;
    const int bg  = mt / 108;
    const int b   = bg >> 1;
    const int g   = bg & 1;
    const int sp0 = (mt % 108) * 128;
    const float* xb = x + (size_t)b * C_ * XSTR + sp0 + tid;

    #pragma unroll 8
    for (int j = 0; j < 64; ++j) {
        const int k = kc * 64 + j;
        const int c = k & 31;
        const int s = k >> 5;
        const int t = (g * 32 + s + 48) & 63;
        const float v = xb[(size_t)c * XSTR + (size_t)t * SP];
        const uint32_t off = swz((uint32_t)tid * 128 + (uint32_t)j * 2);
        *(__half*)((char*)shh + off) = __float2half_rn(v);
    }
    __syncthreads();
    const uint4* s4h = (const uint4*)shh;
    uint4* dh = (uint4*)((char*)g_Xh + (size_t)bx * A_TILE);
    #pragma unroll
    for (int i = tid; i < 1024; i += 128) { dh[i] = s4h[i]; }
}

// ---------------- prepass: W -> split fp16 hi/lo, pre-swizzled B tiles ----------------
__global__ void __launch_bounds__(128) prepass_w(const float* __restrict__ W) {
    const int bx  = blockIdx.x;          // = nt*16 + kc
    const int nt  = bx >> 4;
    const int kc  = bx & 15;
    const int tid = threadIdx.x;
    const int j   = tid & 63;
    char* dh = (char*)g_Wh + (size_t)bx * B_TILE;
    char* dl = (char*)g_Wl + (size_t)bx * B_TILE;
    for (int r = (tid >> 6); r < 256; r += 2) {
        const int o = nt * 256 + r;
        const float v = W[(size_t)o * 1024 + kc * 64 + j];
        const __half hi = __float2half_rn(v);
        const __half lo = __float2half_rn(v - __half2float(hi));
        const uint32_t off = swz((uint32_t)r * 128 + (uint32_t)j * 2);
        *(__half*)(dh + off) = hi;
        *(__half*)(dl + off) = lo;
    }
}

// ---------------- GEMM: mma.sync fp16, CTA 128x256, hh + hl fused K sweep ----------------
DINLINE void issue_loads(int kc, int s, int mt, int nt, int tid, uint32_t smem_base) {
    const char* aH = (const char*)g_Xh + (size_t)(mt * 16 + kc) * A_TILE;
    const char* bH = (const char*)g_Wh + (size_t)(nt * 16 + kc) * B_TILE;
    const char* bL = (const char*)g_Wl + (size_t)(nt * 16 + kc) * B_TILE;
    const uint32_t sAh = smem_base + s * STAGE_BYTES;
    const uint32_t sBh = sAh + A_TILE;
    const uint32_t sBl = sBh + B_TILE;
    #pragma unroll
    for (int i = 0; i < 2; ++i) {
        const uint32_t o = (uint32_t)i * 8192 + (uint32_t)tid * 16;
        cp_async16(sAh + o, aH + o);
    }
    #pragma unroll
    for (int i = 0; i < 4; ++i) {
        const uint32_t o = (uint32_t)i * 8192 + (uint32_t)tid * 16;
        cp_async16(sBh + o, bH + o);
        cp_async16(sBl + o, bL + o);
    }
}

__global__ void __launch_bounds__(512, 1) gemm_k(const float* __restrict__ bias,
                                                 float* __restrict__ out) {
    extern __shared__ __align__(1024) char smem[];
    const uint32_t smem_base = smem_u32(smem);
    const int tid = threadIdx.x;
    const int l   = tid & 31;
    const int wid = tid >> 5;
    const int wm  = wid & 3;     // m 32-block
    const int wn  = wid >> 2;    // n 64-block
    const int bx  = blockIdx.x;
    const int nt  = bx & 3;
    const int mt  = bx >> 2;

    // per-lane ldmatrix address components
    uint32_t a_off[2], a_ph[2];
    #pragma unroll
    for (int mb = 0; mb < 2; ++mb) {
        const int row = wm * 32 + mb * 16 + (l & 15);
        a_off[mb] = (uint32_t)row * 128;
        a_ph[mb]  = (uint32_t)(row & 7) * 16;
    }
    const uint32_t a_half = (uint32_t)(l >> 4) * 16;
    const int bmat = l >> 3;
    uint32_t b_off[4], b_ph[4];
    #pragma unroll
    for (int nb2 = 0; nb2 < 4; ++nb2) {
        const int row = wn * 64 + nb2 * 16 + (bmat >> 1) * 8 + (l & 7);
        b_off[nb2] = (uint32_t)row * 128;
        b_ph[nb2]  = (uint32_t)(row & 7) * 16;
    }
    const uint32_t b_half = (uint32_t)(bmat & 1) * 16;

    float acc[2][8][4];
    #pragma unroll
    for (int mb = 0; mb < 2; ++mb)
        #pragma unroll
        for (int nb = 0; nb < 8; ++nb)
            #pragma unroll
            for (int i = 0; i < 4; ++i) acc[mb][nb][i] = 0.f;

    // prologue: stages 0,1
    issue_loads(0, 0, mt, nt, tid, smem_base); CP_COMMIT();
    issue_loads(1, 1, mt, nt, tid, smem_base); CP_COMMIT();

    for (int it = 0; it < KCHUNKS; ++it) {
        const int s = it & 1;
        CP_WAIT1();
        __syncthreads();

        const uint32_t sAh = smem_base + s * STAGE_BYTES;
        const uint32_t sBh = sAh + A_TILE;
        const uint32_t sBl = sBh + B_TILE;

        #pragma unroll
        for (int kk = 0; kk < 4; ++kk) {
            const uint32_t ka = (uint32_t)kk * 32 + a_half;
            const uint32_t kb = (uint32_t)kk * 32 + b_half;
            uint32_t ah[2][4], bf[8][2];
            // A-hi fragments (shared by hh and hl products)
            #pragma unroll
            for (int mb = 0; mb < 2; ++mb)
                ldsm_x4(ah[mb], sAh + a_off[mb] + (ka ^ a_ph[mb]));
            // B-hi fragments
            #pragma unroll
            for (int nb2 = 0; nb2 < 4; ++nb2) {
                uint32_t r[4];
                ldsm_x4(r, sBh + b_off[nb2] + (kb ^ b_ph[nb2]));
                bf[nb2 * 2][0]     = r[0]; bf[nb2 * 2][1]     = r[1];
                bf[nb2 * 2 + 1][0] = r[2]; bf[nb2 * 2 + 1][1] = r[3];
            }
            // hh
            #pragma unroll
            for (int mb = 0; mb < 2; ++mb)
                #pragma unroll
                for (int nb = 0; nb < 8; ++nb)
                    mma16816(acc[mb][nb], ah[mb], bf[nb][0], bf[nb][1]);
            // B-lo fragments (reuse bf regs), hl (Ah x Bl)
            #pragma unroll
            for (int nb2 = 0; nb2 < 4; ++nb2) {
                uint32_t r[4];
                ldsm_x4(r, sBl + b_off[nb2] + (kb ^ b_ph[nb2]));
                bf[nb2 * 2][0]     = r[0]; bf[nb2 * 2][1]     = r[1];
                bf[nb2 * 2 + 1][0] = r[2]; bf[nb2 * 2 + 1][1] = r[3];
            }
            #pragma unroll
            for (int mb = 0; mb < 2; ++mb)
                #pragma unroll
                for (int nb = 0; nb < 8; ++nb)
                    mma16816(acc[mb][nb], ah[mb], bf[nb][0], bf[nb][1]);
        }

        __syncthreads();
        if (it + 2 < KCHUNKS) issue_loads(it + 2, s, mt, nt, tid, smem_base);
        CP_COMMIT();
    }
    CP_WAIT0();
    __syncthreads();

    // ---------------- epilogue: transpose C via SMEM, coalesced scatter ----------------
    float* sC = (float*)smem;            // 128 rows x 34 floats (padded)
    const int bg = mt / 108;
    const int b  = bg >> 1;
    const int g  = bg & 1;
    const int sp0 = (mt % 108) * 128;

    const int col  = tid >> 4;           // 0..31
    const int rb   = (tid & 15) * 8;     // row base, 8 rows per thread
    float* outB = out + (size_t)b * C_ * XSTR + sp0;

    #pragma unroll
    for (int p = 0; p < 8; ++p) {        // 32-col passes over the 256-wide tile
        if (wn == (p >> 1)) {
            const int nbb = (p & 1) * 4;
            #pragma unroll
            for (int mb = 0; mb < 2; ++mb) {
                #pragma unroll
                for (int nbl = 0; nbl < 4; ++nbl) {
                    const int nb  = nbb + nbl;
                    const int row = wm * 32 + mb * 16 + (l >> 2);
                    const int cc  = nbl * 8 + (l & 3) * 2;
                    *(float2*)&sC[row * 34 + cc]       = *(float2*)&acc[mb][nb][0];
                    *(float2*)&sC[(row + 8) * 34 + cc] = *(float2*)&acc[mb][nb][2];
                }
            }
        }
        __syncthreads();
        {
            const int o  = nt * 256 + p * 32 + col;
            const int sv = o >> 5;
            const int c  = o & 31;
            const int tp = (g * 32 + sv + 48) & 63;
            const float bia = __ldg(&bias[o]);
            float v[8];
            #pragma unroll
            for (int i = 0; i < 8; ++i) v[i] = sC[(rb + i) * 34 + col] + bia;
            float* dst = outB + (size_t)c * XSTR + (size_t)tp * SP + rb;
            *(float4*)&dst[0] = *(float4*)&v[0];
            *(float4*)&dst[4] = *(float4*)&v[4];
        }
        __syncthreads();
    }
}

// ---------------- host ----------------
extern "C" void kernel_launch(void* const* d_in, const int* in_sizes, int n_in,
                              void* d_out, int out_size) {
    const float* x    = (const float*)d_in[0];
    const float* W    = (const float*)d_in[1];
    const float* bias = (const float*)d_in[2];
    float* out = (float*)d_out;

    cudaFuncSetAttribute(gemm_k, cudaFuncAttributeMaxDynamicSharedMemorySize, SMEM_DYN);

    prepass_x<<<MTILES * KCHUNKS, 128>>>(x);                 // 6912 blocks
    prepass_w<<<NTILES * KCHUNKS, 128>>>(W);                 // 64 blocks
    gemm_k<<<MTILES * NTILES, 512, SMEM_DYN>>>(bias, out);   // 1728 blocks
}